// round 7
// baseline (speedup 1.0000x reference)
#include <cuda_runtime.h>
#include <cuda_bf16.h>
#include <cstdint>

#define SLEN   1024
#define BSZ    32
#define HID    1024
#define INDIM  1024
#define M_TOTAL (SLEN * BSZ)   // 32768
#define NFUSED  (2 * HID)      // z|f stacked

// -------- scratch (__device__ globals) --------
__device__ float g_z [(size_t)M_TOTAL * HID];
__device__ float g_f [(size_t)M_TOTAL * HID];
// A in bf16 hi/lo fragment order: [mt:2048][kt:64][h:2][lane:32] x uint4
__device__ uint4 g_abf[(size_t)2048 * 64 * 2 * 32];
// B fused z|f: [nt:256][kt:64][lane:32] x uint4 {b0h,b1h,b0l,b1l}
__device__ uint4 g_bbf[(size_t)256 * 64 * 32];

__device__ __forceinline__ uint32_t pk(__nv_bfloat16 a, __nv_bfloat16 b) {
    uint16_t ua = *(uint16_t*)&a, ub = *(uint16_t*)&b;
    return (uint32_t)ua | ((uint32_t)ub << 16);
}
__device__ __forceinline__ void hilo(float v, __nv_bfloat16& h, __nv_bfloat16& l) {
    h = __float2bfloat16_rn(v);
    l = __float2bfloat16_rn(v - __bfloat162float(h));
}
__device__ __forceinline__ void cp16(uint32_t dst, const void* src) {
    asm volatile("cp.async.cg.shared.global [%0], [%1], 16;" :: "r"(dst), "l"(src));
}
__device__ __forceinline__ void cp8(uint32_t dst, const void* src) {
    asm volatile("cp.async.ca.shared.global [%0], [%1], 8;" :: "r"(dst), "l"(src));
}

// ============ prep A: x -> bf16 hi/lo fragments ============
__global__ __launch_bounds__(256)
void prep_a(const float* __restrict__ x, uint4* __restrict__ Af) {
    size_t u = (size_t)blockIdx.x * 256 + threadIdx.x;   // (mt,kt,lane): 4,194,304
    int lane = (int)(u & 31);
    int kt   = (int)((u >> 5) & 63);
    int mt   = (int)(u >> 11);
    int g = lane >> 2, tg = lane & 3;
    const float* r0 = x + (size_t)(mt * 16 + g) * INDIM + kt * 16;
    const float* r1 = r0 + 8 * INDIM;
    float2 p00 = *(const float2*)(r0 + 2 * tg);         // a0: (g,   2tg..)
    float2 p10 = *(const float2*)(r1 + 2 * tg);         // a1: (g+8, 2tg..)
    float2 p01 = *(const float2*)(r0 + 8 + 2 * tg);     // a2: (g,   8+2tg..)
    float2 p11 = *(const float2*)(r1 + 8 + 2 * tg);     // a3: (g+8, 8+2tg..)
    __nv_bfloat16 h0,l0,h1,l1,h2,l2,h3,l3,h4,l4,h5,l5,h6,l6,h7,l7;
    hilo(p00.x,h0,l0); hilo(p00.y,h1,l1);
    hilo(p10.x,h2,l2); hilo(p10.y,h3,l3);
    hilo(p01.x,h4,l4); hilo(p01.y,h5,l5);
    hilo(p11.x,h6,l6); hilo(p11.y,h7,l7);
    uint4 hi = make_uint4(pk(h0,h1), pk(h2,h3), pk(h4,h5), pk(h6,h7));
    uint4 lo = make_uint4(pk(l0,l1), pk(l2,l3), pk(l4,l5), pk(l6,l7));
    size_t base = (((size_t)mt * 64 + kt) * 2) * 32 + lane;
    Af[base]      = hi;
    Af[base + 32] = lo;
}

// ============ prep B: weights (fused z|f) -> bf16 hi/lo fragments ============
__global__ __launch_bounds__(256)
void prep_b(const float* __restrict__ wz, const float* __restrict__ wf,
            uint4* __restrict__ Bf) {
    size_t u = (size_t)blockIdx.x * 256 + threadIdx.x;   // (nt,kt,lane): 524,288
    int lane = (int)(u & 31);
    int kt   = (int)((u >> 5) & 63);
    int nt   = (int)(u >> 11);
    int g = lane >> 2, tg = lane & 3;
    int n = nt * 8 + g;
    const float* row = (n < HID) ? (wz + (size_t)n * INDIM)
                                 : (wf + (size_t)(n - HID) * INDIM);
    float2 q0 = *(const float2*)(row + kt * 16 + 2 * tg);       // b0: k=2tg..
    float2 q1 = *(const float2*)(row + kt * 16 + 8 + 2 * tg);   // b1: k=8+2tg..
    __nv_bfloat16 h0,l0,h1,l1,h2,l2,h3,l3;
    hilo(q0.x,h0,l0); hilo(q0.y,h1,l1);
    hilo(q1.x,h2,l2); hilo(q1.y,h3,l3);
    Bf[u] = make_uint4(pk(h0,h1), pk(h2,h3), pk(l0,l1), pk(l2,l3));
}

// ============ bf16 hi/lo GEMM ============
// CTA 256 thr (8 warps 2x4), tile 128 x 256(fused), KC=32 (2 kt of K=16), 3-stage
#define BM 128
#define BN 256
#define NCH 32                    // 1024 / 32
#define A_STAGE 16384             // 8mtl*2ktl*2h*32lane*16B
#define B_STAGE 32768             // 32ntl*2ktl*32lane*16B
#define STAGE_BYTES (A_STAGE + B_STAGE)
#define SMEM_BYTES  (3 * STAGE_BYTES)    // 147456

__device__ __forceinline__ void mma16(float* d, const uint32_t* a,
                                      uint32_t b0, uint32_t b1) {
    asm volatile(
        "mma.sync.aligned.m16n8k16.row.col.f32.bf16.bf16.f32 "
        "{%0,%1,%2,%3}, {%4,%5,%6,%7}, {%8,%9}, {%0,%1,%2,%3};"
        : "+f"(d[0]), "+f"(d[1]), "+f"(d[2]), "+f"(d[3])
        : "r"(a[0]), "r"(a[1]), "r"(a[2]), "r"(a[3]), "r"(b0), "r"(b1));
}

__global__ __launch_bounds__(256, 1)
void gemm_tc(const uint4* __restrict__ Af, const uint4* __restrict__ Bf,
             const float* __restrict__ bz, const float* __restrict__ bfb) {
    extern __shared__ char smemc[];
    const int tid  = threadIdx.x;
    const int lane = tid & 31;
    const int wid  = tid >> 5;
    const int wm   = wid >> 2;                 // 0..1
    const int wn   = wid & 3;                  // 0..3
    const int mt0  = blockIdx.y * (BM / 16);   // m16-tile base
    const int nt0  = blockIdx.x * (BN / 8);    // n8-tile base

    float d[4][8][4];
#pragma unroll
    for (int i = 0; i < 4; i++)
#pragma unroll
        for (int j = 0; j < 8; j++)
#pragma unroll
            for (int q = 0; q < 4; q++) d[i][j][q] = 0.f;

    auto load_chunk = [&](int st, int c) {
        char* stA = smemc + st * STAGE_BYTES;
        char* stB = stA + A_STAGE;
        const int ktg0 = c * 2;
#pragma unroll
        for (int t = 0; t < 4; t++) {          // A: 1024 x 16B
            int idx = tid + t * 256;
            int l = idx & 31, h = (idx >> 5) & 1, ktl = (idx >> 6) & 1, mtl = idx >> 7;
            const uint4* src = Af +
                ((((size_t)(mt0 + mtl) * 64) + (ktg0 + ktl)) * 2 + h) * 32 + l;
            cp16((uint32_t)__cvta_generic_to_shared(stA + idx * 16), src);
        }
#pragma unroll
        for (int t = 0; t < 8; t++) {          // B: 2048 x 16B
            int idx = tid + t * 256;
            int l = idx & 31, ktl = (idx >> 5) & 1, ntl = idx >> 6;
            const uint4* src = Bf +
                (((size_t)(nt0 + ntl) * 64) + (ktg0 + ktl)) * 32 + l;
            cp16((uint32_t)__cvta_generic_to_shared(stB + idx * 16), src);
        }
        asm volatile("cp.async.commit_group;" ::: "memory");
    };

    load_chunk(0, 0);
    load_chunk(1, 1);

    for (int c = 0; c < NCH; ++c) {
        if (c + 1 < NCH) asm volatile("cp.async.wait_group 1;" ::: "memory");
        else             asm volatile("cp.async.wait_group 0;" ::: "memory");
        __syncthreads();
        // issue next DMA first (stage freed by the sync above), overlap with compute
        if (c + 2 < NCH) load_chunk((c + 2) % 3, c + 2);

        const int st = c % 3;
        const char* stA = smemc + st * STAGE_BYTES;
        const char* stB = stA + A_STAGE;
#pragma unroll
        for (int ktl = 0; ktl < 2; ktl++) {
            uint32_t ah[4][4], al[4][4];
#pragma unroll
            for (int i = 0; i < 4; i++) {
                int mtl = wm * 4 + i;
                uint4 h4 = *(const uint4*)(stA + (((mtl * 2 + ktl) * 2 + 0) * 32 + lane) * 16);
                uint4 l4 = *(const uint4*)(stA + (((mtl * 2 + ktl) * 2 + 1) * 32 + lane) * 16);
                ah[i][0]=h4.x; ah[i][1]=h4.y; ah[i][2]=h4.z; ah[i][3]=h4.w;
                al[i][0]=l4.x; al[i][1]=l4.y; al[i][2]=l4.z; al[i][3]=l4.w;
            }
#pragma unroll
            for (int j = 0; j < 8; j++) {
                int ntl = wn * 8 + j;
                uint4 b4 = *(const uint4*)(stB + (((ntl * 2 + ktl) * 32) + lane) * 16);
#pragma unroll
                for (int i = 0; i < 4; i++) {
                    mma16(d[i][j], ah[i], b4.x, b4.y);   // hi*hi
                    mma16(d[i][j], al[i], b4.x, b4.y);   // lo*hi
                    mma16(d[i][j], ah[i], b4.z, b4.w);   // hi*lo
                }
            }
        }
    }

    // ---- epilogue ----
    const int g  = lane >> 2, tg = lane & 3;
    const int n0f = nt0 * 8;
    const bool isF = (n0f >= HID);
    float*       outp  = isF ? g_f : g_z;
    const float* bp    = isF ? bfb : bz;
    const float  scale = isF ? 0.5f : 1.0f;
    const int colBase  = (n0f - (isF ? HID : 0)) + wn * 64;

#pragma unroll
    for (int j = 0; j < 8; j++) {
        const int col = colBase + j * 8 + 2 * tg;
        const float2 bbv = *(const float2*)(bp + col);
#pragma unroll
        for (int i = 0; i < 4; i++) {
            const size_t row = (size_t)blockIdx.y * BM + wm * 64 + i * 16 + g;
            float2 v0, v1;
            v0.x = scale * (d[i][j][0] + bbv.x);
            v0.y = scale * (d[i][j][1] + bbv.y);
            v1.x = scale * (d[i][j][2] + bbv.x);
            v1.y = scale * (d[i][j][3] + bbv.y);
            *(float2*)(outp + row * HID + col)       = v0;
            *(float2*)(outp + (row + 8) * HID + col) = v1;
        }
    }
}

// ============ scan: cp.async ring, 2 ch/thread, 64 thr/block ============
#define PF 32

__device__ __forceinline__ float tanh_fast(float v) {
    float r;
    asm("tanh.approx.f32 %0, %1;" : "=f"(r) : "f"(v));
    return r;
}

__global__ __launch_bounds__(64)
void scan_kernel(const float* __restrict__ state,
                 const float* __restrict__ wvz, const float* __restrict__ wvf,
                 float* __restrict__ out) {
    __shared__ float2 buf[PF][64][2];   // [stage][thread][0=z,1=f] = 32KB
    const int t = threadIdx.x;
    const int C = (blockIdx.x * 64 + t) * 2;
    const int h0 = C & (HID - 1);

    float cell[2], wz[2], wfh[2];
#pragma unroll
    for (int c = 0; c < 2; c++) {
        cell[c] = state[C + c];
        wz[c]   = wvz[h0 + c];
        wfh[c]  = 0.5f * wvf[h0 + c];
    }

    const float* zsrc = g_z + C;
    const float* fsrc = g_f + C;

#pragma unroll 4
    for (int s = 0; s < PF; s++) {
        cp8((uint32_t)__cvta_generic_to_shared(&buf[s][t][0]), zsrc + (size_t)s * M_TOTAL);
        cp8((uint32_t)__cvta_generic_to_shared(&buf[s][t][1]), fsrc + (size_t)s * M_TOTAL);
        asm volatile("cp.async.commit_group;" ::: "memory");
    }

#pragma unroll 1
    for (int s = 0; s < SLEN; s++) {
        asm volatile("cp.async.wait_group %0;" :: "n"(PF - 1) : "memory");
        const int slot = s & (PF - 1);
        float2 z2 = buf[slot][t][0];
        float2 f2 = buf[slot][t][1];
        if (s + PF < SLEN) {
            cp8((uint32_t)__cvta_generic_to_shared(&buf[slot][t][0]),
                zsrc + (size_t)(s + PF) * M_TOTAL);
            cp8((uint32_t)__cvta_generic_to_shared(&buf[slot][t][1]),
                fsrc + (size_t)(s + PF) * M_TOTAL);
        }
        asm volatile("cp.async.commit_group;" ::: "memory");

        float zv[2] = {z2.x, z2.y};
        float fv[2] = {f2.x, f2.y};
        float2 o;
        float* ov = (float*)&o;
#pragma unroll
        for (int c = 0; c < 2; c++) {
            float zpart = tanh_fast(fmaf(wz[c],  cell[c], zv[c]));
            float tt    = tanh_fast(fmaf(wfh[c], cell[c], fv[c]));
            float fpart = fmaf(0.5f, tt, 0.5f);
            cell[c] = fmaf(fpart, cell[c] - zpart, zpart);
            ov[c] = cell[c];
        }
        *(float2*)(out + (size_t)s * M_TOTAL + C) = o;
    }
}

// ============ launch ============
extern "C" void kernel_launch(void* const* d_in, const int* in_sizes, int n_in,
                              void* d_out, int out_size) {
    const float* x      = (const float*)d_in[0];
    const float* state  = (const float*)d_in[1];
    const float* wm_z   = (const float*)d_in[2];
    const float* wm_f   = (const float*)d_in[3];
    const float* wv_z   = (const float*)d_in[4];
    const float* wv_f   = (const float*)d_in[5];
    const float* bias_z = (const float*)d_in[6];
    const float* bias_f = (const float*)d_in[7];
    float* out = (float*)d_out;

    uint4 *af, *bf;
    cudaGetSymbolAddress((void**)&af, g_abf);
    cudaGetSymbolAddress((void**)&bf, g_bbf);

    cudaFuncSetAttribute(gemm_tc, cudaFuncAttributeMaxDynamicSharedMemorySize, SMEM_BYTES);

    prep_a<<<16384, 256>>>(x, af);          // 2048*64*32 / 256
    prep_b<<<2048, 256>>>(wm_z, wm_f, bf);  // 256*64*32 / 256

    dim3 grid(NFUSED / BN, M_TOTAL / BM);   // (8, 256)
    gemm_tc<<<grid, 256, SMEM_BYTES>>>(af, bf, bias_z, bias_f);

    scan_kernel<<<256, 64>>>(state, wv_z, wv_f, out);
}

// round 8
// speedup vs baseline: 2.1290x; 2.1290x over previous
#include <cuda_runtime.h>
#include <cuda_fp16.h>
#include <cstdint>

#define SLEN   1024
#define BSZ    32
#define HID    1024
#define INDIM  1024
#define M_TOTAL (SLEN * BSZ)   // 32768
#define NFUSED  (2 * HID)      // z|f stacked

// -------- scratch (__device__ globals) --------
__device__ float g_z [(size_t)M_TOTAL * HID];
__device__ float g_f [(size_t)M_TOTAL * HID];
// A fp16 fragments: [mt:2048][kt:64][lane:32] x uint4 {a0,a1,a2,a3}
__device__ uint4 g_ah[(size_t)2048 * 64 * 32];
// B fp16 fragments fused z|f: [nt:256][kp:32][lane:32] x uint4 {kt0.b0,kt0.b1,kt1.b0,kt1.b1}
__device__ uint4 g_bh[(size_t)256 * 32 * 32];

__device__ __forceinline__ uint32_t pkh(float a, float b) {
    __half2 h = __floats2half2_rn(a, b);
    return *(uint32_t*)&h;
}
__device__ __forceinline__ void cp16(uint32_t dst, const void* src) {
    asm volatile("cp.async.cg.shared.global [%0], [%1], 16;" :: "r"(dst), "l"(src));
}
__device__ __forceinline__ void cp8(uint32_t dst, const void* src) {
    asm volatile("cp.async.ca.shared.global [%0], [%1], 8;" :: "r"(dst), "l"(src));
}

// ============ prep A: x -> fp16 m16n8k16 A-fragments ============
__global__ __launch_bounds__(256)
void prep_a(const float* __restrict__ x, uint4* __restrict__ Af) {
    size_t u = (size_t)blockIdx.x * 256 + threadIdx.x;   // (mt,kt,lane): 4,194,304
    int lane = (int)(u & 31);
    int kt   = (int)((u >> 5) & 63);
    int mt   = (int)(u >> 11);
    int g = lane >> 2, tg = lane & 3;
    const float* r0 = x + (size_t)(mt * 16 + g) * INDIM + kt * 16;
    const float* r1 = r0 + 8 * INDIM;
    float2 p00 = *(const float2*)(r0 + 2 * tg);        // a0: (g,   2tg..)
    float2 p10 = *(const float2*)(r1 + 2 * tg);        // a1: (g+8, 2tg..)
    float2 p01 = *(const float2*)(r0 + 8 + 2 * tg);    // a2: (g,   8+2tg..)
    float2 p11 = *(const float2*)(r1 + 8 + 2 * tg);    // a3: (g+8, 8+2tg..)
    Af[u] = make_uint4(pkh(p00.x, p00.y), pkh(p10.x, p10.y),
                       pkh(p01.x, p01.y), pkh(p11.x, p11.y));
}

// ============ prep B: weights (fused z|f) -> fp16 B-fragments, kt-pairs ============
__global__ __launch_bounds__(256)
void prep_b(const float* __restrict__ wz, const float* __restrict__ wf,
            uint4* __restrict__ Bf) {
    size_t u = (size_t)blockIdx.x * 256 + threadIdx.x;   // (nt,kp,lane): 262,144
    int lane = (int)(u & 31);
    int kp   = (int)((u >> 5) & 31);
    int nt   = (int)(u >> 10);
    int g = lane >> 2, tg = lane & 3;
    int n = nt * 8 + g;
    const float* row = (n < HID) ? (wz + (size_t)n * INDIM)
                                 : (wf + (size_t)(n - HID) * INDIM);
    const float* c0 = row + kp * 32;         // kt0 = 2kp
    float2 q00 = *(const float2*)(c0 + 2 * tg);            // kt0.b0
    float2 q01 = *(const float2*)(c0 + 8 + 2 * tg);        // kt0.b1
    float2 q10 = *(const float2*)(c0 + 16 + 2 * tg);       // kt1.b0
    float2 q11 = *(const float2*)(c0 + 24 + 2 * tg);       // kt1.b1
    Bf[u] = make_uint4(pkh(q00.x, q00.y), pkh(q01.x, q01.y),
                       pkh(q10.x, q10.y), pkh(q11.x, q11.y));
}

// ============ fp16 single-term GEMM ============
// CTA 256 thr (8 warps 2x4), tile 128 x 256(fused), KC=64 (4 k16-steps), 3-stage
#define BM 128
#define BN 256
#define NCH 16                    // 1024 / 64
#define A_STAGE 16384             // 8mtl*4kt*32lane*16B
#define B_STAGE 32768             // 32ntl*2kp*32lane*16B
#define STAGE_BYTES (A_STAGE + B_STAGE)
#define SMEM_BYTES  (3 * STAGE_BYTES)    // 147456

__device__ __forceinline__ void mma16(float* d, const uint32_t* a,
                                      uint32_t b0, uint32_t b1) {
    asm volatile(
        "mma.sync.aligned.m16n8k16.row.col.f32.f16.f16.f32 "
        "{%0,%1,%2,%3}, {%4,%5,%6,%7}, {%8,%9}, {%0,%1,%2,%3};"
        : "+f"(d[0]), "+f"(d[1]), "+f"(d[2]), "+f"(d[3])
        : "r"(a[0]), "r"(a[1]), "r"(a[2]), "r"(a[3]), "r"(b0), "r"(b1));
}

__global__ __launch_bounds__(256, 1)
void gemm_tc(const uint4* __restrict__ Af, const uint4* __restrict__ Bf,
             const float* __restrict__ bz, const float* __restrict__ bfb) {
    extern __shared__ char smemc[];
    const int tid  = threadIdx.x;
    const int lane = tid & 31;
    const int wid  = tid >> 5;
    const int wm   = wid >> 2;                 // 0..1
    const int wn   = wid & 3;                  // 0..3
    const int mt0  = blockIdx.y * (BM / 16);
    const int nt0  = blockIdx.x * (BN / 8);

    float d[4][8][4];
#pragma unroll
    for (int i = 0; i < 4; i++)
#pragma unroll
        for (int j = 0; j < 8; j++)
#pragma unroll
            for (int q = 0; q < 4; q++) d[i][j][q] = 0.f;

    auto load_chunk = [&](int st, int c) {
        char* stA = smemc + st * STAGE_BYTES;
        char* stB = stA + A_STAGE;
        const int ktg0 = c * 4;   // k16-step base
        const int kpg0 = c * 2;   // kt-pair base
#pragma unroll
        for (int t = 0; t < 4; t++) {          // A: 1024 x 16B
            int idx = tid + t * 256;
            int l = idx & 31, kt = (idx >> 5) & 3, mtl = idx >> 7;
            const uint4* src = Af +
                (((size_t)(mt0 + mtl) * 64) + (ktg0 + kt)) * 32 + l;
            cp16((uint32_t)__cvta_generic_to_shared(stA + idx * 16), src);
        }
#pragma unroll
        for (int t = 0; t < 8; t++) {          // B: 2048 x 16B
            int idx = tid + t * 256;
            int l = idx & 31, kp = (idx >> 5) & 1, ntl = idx >> 6;
            const uint4* src = Bf +
                (((size_t)(nt0 + ntl) * 32) + (kpg0 + kp)) * 32 + l;
            cp16((uint32_t)__cvta_generic_to_shared(stB + idx * 16), src);
        }
        asm volatile("cp.async.commit_group;" ::: "memory");
    };

    load_chunk(0, 0);
    load_chunk(1, 1);

    for (int c = 0; c < NCH; ++c) {
        if (c + 1 < NCH) asm volatile("cp.async.wait_group 1;" ::: "memory");
        else             asm volatile("cp.async.wait_group 0;" ::: "memory");
        __syncthreads();
        if (c + 2 < NCH) load_chunk((c + 2) % 3, c + 2);   // overlap with compute

        const int st = c % 3;
        const char* stA = smemc + st * STAGE_BYTES;
        const char* stB = stA + A_STAGE;
#pragma unroll
        for (int kp = 0; kp < 2; kp++) {
            uint32_t a0[4][4], a1[4][4];       // frags for kt=2kp, 2kp+1
#pragma unroll
            for (int i = 0; i < 4; i++) {
                int mtl = wm * 4 + i;
                uint4 v0 = *(const uint4*)(stA + ((mtl * 4 + 2 * kp)     * 32 + lane) * 16);
                uint4 v1 = *(const uint4*)(stA + ((mtl * 4 + 2 * kp + 1) * 32 + lane) * 16);
                a0[i][0]=v0.x; a0[i][1]=v0.y; a0[i][2]=v0.z; a0[i][3]=v0.w;
                a1[i][0]=v1.x; a1[i][1]=v1.y; a1[i][2]=v1.z; a1[i][3]=v1.w;
            }
#pragma unroll
            for (int j = 0; j < 8; j++) {
                int ntl = wn * 8 + j;
                uint4 b4 = *(const uint4*)(stB + ((ntl * 2 + kp) * 32 + lane) * 16);
#pragma unroll
                for (int i = 0; i < 4; i++) {
                    mma16(d[i][j], a0[i], b4.x, b4.y);   // kt = 2kp
                    mma16(d[i][j], a1[i], b4.z, b4.w);   // kt = 2kp+1
                }
            }
        }
    }

    // ---- epilogue: +bias, 0.5x for f-half ----
    const int g  = lane >> 2, tg = lane & 3;
    const int n0f = nt0 * 8;
    const bool isF = (n0f >= HID);
    float*       outp  = isF ? g_f : g_z;
    const float* bp    = isF ? bfb : bz;
    const float  scale = isF ? 0.5f : 1.0f;
    const int colBase  = (n0f - (isF ? HID : 0)) + wn * 64;

#pragma unroll
    for (int j = 0; j < 8; j++) {
        const int col = colBase + j * 8 + 2 * tg;
        const float2 bbv = *(const float2*)(bp + col);
#pragma unroll
        for (int i = 0; i < 4; i++) {
            const size_t row = (size_t)blockIdx.y * BM + wm * 64 + i * 16 + g;
            float2 v0, v1;
            v0.x = scale * (d[i][j][0] + bbv.x);
            v0.y = scale * (d[i][j][1] + bbv.y);
            v1.x = scale * (d[i][j][2] + bbv.x);
            v1.y = scale * (d[i][j][3] + bbv.y);
            *(float2*)(outp + row * HID + col)       = v0;
            *(float2*)(outp + (row + 8) * HID + col) = v1;
        }
    }
}

// ============ scan: cp.async ring, 2 ch/thread, 64 thr/block (unchanged R7) ============
#define PF 32

__device__ __forceinline__ float tanh_fast(float v) {
    float r;
    asm("tanh.approx.f32 %0, %1;" : "=f"(r) : "f"(v));
    return r;
}

__global__ __launch_bounds__(64)
void scan_kernel(const float* __restrict__ state,
                 const float* __restrict__ wvz, const float* __restrict__ wvf,
                 float* __restrict__ out) {
    __shared__ float2 buf[PF][64][2];   // 32KB
    const int t = threadIdx.x;
    const int C = (blockIdx.x * 64 + t) * 2;
    const int h0 = C & (HID - 1);

    float cell[2], wz[2], wfh[2];
#pragma unroll
    for (int c = 0; c < 2; c++) {
        cell[c] = state[C + c];
        wz[c]   = wvz[h0 + c];
        wfh[c]  = 0.5f * wvf[h0 + c];
    }

    const float* zsrc = g_z + C;
    const float* fsrc = g_f + C;

#pragma unroll 4
    for (int s = 0; s < PF; s++) {
        cp8((uint32_t)__cvta_generic_to_shared(&buf[s][t][0]), zsrc + (size_t)s * M_TOTAL);
        cp8((uint32_t)__cvta_generic_to_shared(&buf[s][t][1]), fsrc + (size_t)s * M_TOTAL);
        asm volatile("cp.async.commit_group;" ::: "memory");
    }

#pragma unroll 1
    for (int s = 0; s < SLEN; s++) {
        asm volatile("cp.async.wait_group %0;" :: "n"(PF - 1) : "memory");
        const int slot = s & (PF - 1);
        float2 z2 = buf[slot][t][0];
        float2 f2 = buf[slot][t][1];
        if (s + PF < SLEN) {
            cp8((uint32_t)__cvta_generic_to_shared(&buf[slot][t][0]),
                zsrc + (size_t)(s + PF) * M_TOTAL);
            cp8((uint32_t)__cvta_generic_to_shared(&buf[slot][t][1]),
                fsrc + (size_t)(s + PF) * M_TOTAL);
        }
        asm volatile("cp.async.commit_group;" ::: "memory");

        float zv[2] = {z2.x, z2.y};
        float fv[2] = {f2.x, f2.y};
        float2 o;
        float* ov = (float*)&o;
#pragma unroll
        for (int c = 0; c < 2; c++) {
            float zpart = tanh_fast(fmaf(wz[c],  cell[c], zv[c]));
            float tt    = tanh_fast(fmaf(wfh[c], cell[c], fv[c]));
            float fpart = fmaf(0.5f, tt, 0.5f);
            cell[c] = fmaf(fpart, cell[c] - zpart, zpart);
            ov[c] = cell[c];
        }
        *(float2*)(out + (size_t)s * M_TOTAL + C) = o;
    }
}

// ============ launch ============
extern "C" void kernel_launch(void* const* d_in, const int* in_sizes, int n_in,
                              void* d_out, int out_size) {
    const float* x      = (const float*)d_in[0];
    const float* state  = (const float*)d_in[1];
    const float* wm_z   = (const float*)d_in[2];
    const float* wm_f   = (const float*)d_in[3];
    const float* wv_z   = (const float*)d_in[4];
    const float* wv_f   = (const float*)d_in[5];
    const float* bias_z = (const float*)d_in[6];
    const float* bias_f = (const float*)d_in[7];
    float* out = (float*)d_out;

    uint4 *af, *bf;
    cudaGetSymbolAddress((void**)&af, g_ah);
    cudaGetSymbolAddress((void**)&bf, g_bh);

    cudaFuncSetAttribute(gemm_tc, cudaFuncAttributeMaxDynamicSharedMemorySize, SMEM_BYTES);

    prep_a<<<16384, 256>>>(x, af);          // 2048*64*32 / 256
    prep_b<<<1024, 256>>>(wm_z, wm_f, bf);  // 256*32*32 / 256

    dim3 grid(NFUSED / BN, M_TOTAL / BM);   // (8, 256)
    gemm_tc<<<grid, 256, SMEM_BYTES>>>(af, bf, bias_z, bias_f);

    scan_kernel<<<256, 64>>>(state, wv_z, wv_f, out);
}

// round 9
// speedup vs baseline: 2.2804x; 1.0711x over previous
#include <cuda_runtime.h>
#include <cuda_fp16.h>
#include <cstdint>

#define SLEN   1024
#define BSZ    32
#define HID    1024
#define INDIM  1024
#define M_TOTAL (SLEN * BSZ)   // 32768
#define NFUSED  (2 * HID)      // z|f stacked

// -------- scratch (__device__ globals) --------
__device__ float g_z [(size_t)M_TOTAL * HID];
__device__ float g_f [(size_t)M_TOTAL * HID];
// A fp16 fragments: [mt:2048][kt:64][lane:32] x uint4 {a0,a1,a2,a3}
__device__ uint4 g_ah[(size_t)2048 * 64 * 32];
// B fp16 fragments fused z|f: [nt:256][kp:32][lane:32] x uint4 {kt0.b0,kt0.b1,kt1.b0,kt1.b1}
__device__ uint4 g_bh[(size_t)256 * 32 * 32];

__device__ __forceinline__ uint32_t pkh(float a, float b) {
    __half2 h = __floats2half2_rn(a, b);
    return *(uint32_t*)&h;
}
__device__ __forceinline__ void cp16(uint32_t dst, const void* src) {
    asm volatile("cp.async.cg.shared.global [%0], [%1], 16;" :: "r"(dst), "l"(src));
}
__device__ __forceinline__ void cp4(uint32_t dst, const void* src) {
    asm volatile("cp.async.ca.shared.global [%0], [%1], 4;" :: "r"(dst), "l"(src));
}

// ============ prep A: x -> fp16 m16n8k16 A-fragments ============
__global__ __launch_bounds__(256)
void prep_a(const float* __restrict__ x, uint4* __restrict__ Af) {
    size_t u = (size_t)blockIdx.x * 256 + threadIdx.x;   // (mt,kt,lane): 4,194,304
    int lane = (int)(u & 31);
    int kt   = (int)((u >> 5) & 63);
    int mt   = (int)(u >> 11);
    int g = lane >> 2, tg = lane & 3;
    const float* r0 = x + (size_t)(mt * 16 + g) * INDIM + kt * 16;
    const float* r1 = r0 + 8 * INDIM;
    float2 p00 = *(const float2*)(r0 + 2 * tg);
    float2 p10 = *(const float2*)(r1 + 2 * tg);
    float2 p01 = *(const float2*)(r0 + 8 + 2 * tg);
    float2 p11 = *(const float2*)(r1 + 8 + 2 * tg);
    Af[u] = make_uint4(pkh(p00.x, p00.y), pkh(p10.x, p10.y),
                       pkh(p01.x, p01.y), pkh(p11.x, p11.y));
}

// ============ prep B: weights (fused z|f) -> fp16 B-fragments, kt-pairs ============
__global__ __launch_bounds__(256)
void prep_b(const float* __restrict__ wz, const float* __restrict__ wf,
            uint4* __restrict__ Bf) {
    size_t u = (size_t)blockIdx.x * 256 + threadIdx.x;   // (nt,kp,lane): 262,144
    int lane = (int)(u & 31);
    int kp   = (int)((u >> 5) & 31);
    int nt   = (int)(u >> 10);
    int g = lane >> 2, tg = lane & 3;
    int n = nt * 8 + g;
    const float* row = (n < HID) ? (wz + (size_t)n * INDIM)
                                 : (wf + (size_t)(n - HID) * INDIM);
    const float* c0 = row + kp * 32;
    float2 q00 = *(const float2*)(c0 + 2 * tg);
    float2 q01 = *(const float2*)(c0 + 8 + 2 * tg);
    float2 q10 = *(const float2*)(c0 + 16 + 2 * tg);
    float2 q11 = *(const float2*)(c0 + 24 + 2 * tg);
    Bf[u] = make_uint4(pkh(q00.x, q00.y), pkh(q01.x, q01.y),
                       pkh(q10.x, q10.y), pkh(q11.x, q11.y));
}

// ============ fp16 GEMM, 128x128 tile, 2 CTAs/SM ============
#define BM 128
#define BN 128
#define NCH 16                    // 1024 / 64 (KC=64 = 4 k16-steps)
#define A_STAGE 16384             // 8mtl*4kt*32lane*16B
#define B_STAGE 16384             // 16ntl*2kp*32lane*16B
#define STAGE_BYTES (A_STAGE + B_STAGE)
#define SMEM_BYTES  (3 * STAGE_BYTES)    // 98304 -> 2 CTAs/SM

__device__ __forceinline__ void mma16(float* d, const uint32_t* a,
                                      uint32_t b0, uint32_t b1) {
    asm volatile(
        "mma.sync.aligned.m16n8k16.row.col.f32.f16.f16.f32 "
        "{%0,%1,%2,%3}, {%4,%5,%6,%7}, {%8,%9}, {%0,%1,%2,%3};"
        : "+f"(d[0]), "+f"(d[1]), "+f"(d[2]), "+f"(d[3])
        : "r"(a[0]), "r"(a[1]), "r"(a[2]), "r"(a[3]), "r"(b0), "r"(b1));
}

__global__ __launch_bounds__(256, 2)
void gemm_tc(const uint4* __restrict__ Af, const uint4* __restrict__ Bf,
             const float* __restrict__ bz, const float* __restrict__ bfb) {
    extern __shared__ char smemc[];
    const int tid  = threadIdx.x;
    const int lane = tid & 31;
    const int wid  = tid >> 5;
    const int wm   = wid >> 2;                 // 0..1 : 64 M-rows
    const int wn   = wid & 3;                  // 0..3 : 32 N-cols
    const int mt0  = blockIdx.y * (BM / 16);   // 8 m16-tiles
    const int nt0  = blockIdx.x * (BN / 8);    // 16 n8-tiles

    float d[4][4][4];
#pragma unroll
    for (int i = 0; i < 4; i++)
#pragma unroll
        for (int j = 0; j < 4; j++)
#pragma unroll
            for (int q = 0; q < 4; q++) d[i][j][q] = 0.f;

    auto load_chunk = [&](int st, int c) {
        char* stA = smemc + st * STAGE_BYTES;
        char* stB = stA + A_STAGE;
        const int ktg0 = c * 4;
        const int kpg0 = c * 2;
#pragma unroll
        for (int t = 0; t < 4; t++) {          // A: 1024 x 16B
            int idx = tid + t * 256;
            int l = idx & 31, kt = (idx >> 5) & 3, mtl = idx >> 7;
            const uint4* src = Af +
                (((size_t)(mt0 + mtl) * 64) + (ktg0 + kt)) * 32 + l;
            cp16((uint32_t)__cvta_generic_to_shared(stA + idx * 16), src);
        }
#pragma unroll
        for (int t = 0; t < 4; t++) {          // B: 1024 x 16B
            int idx = tid + t * 256;
            int l = idx & 31, kp = (idx >> 5) & 1, ntl = idx >> 6;
            const uint4* src = Bf +
                (((size_t)(nt0 + ntl) * 32) + (kpg0 + kp)) * 32 + l;
            cp16((uint32_t)__cvta_generic_to_shared(stB + idx * 16), src);
        }
        asm volatile("cp.async.commit_group;" ::: "memory");
    };

    load_chunk(0, 0);
    load_chunk(1, 1);

    for (int c = 0; c < NCH; ++c) {
        if (c + 1 < NCH) asm volatile("cp.async.wait_group 1;" ::: "memory");
        else             asm volatile("cp.async.wait_group 0;" ::: "memory");
        __syncthreads();
        if (c + 2 < NCH) load_chunk((c + 2) % 3, c + 2);

        const int st = c % 3;
        const char* stA = smemc + st * STAGE_BYTES;
        const char* stB = stA + A_STAGE;
#pragma unroll
        for (int kp = 0; kp < 2; kp++) {
            uint32_t a0[4][4], a1[4][4];
#pragma unroll
            for (int i = 0; i < 4; i++) {
                int mtl = wm * 4 + i;
                uint4 v0 = *(const uint4*)(stA + ((mtl * 4 + 2 * kp)     * 32 + lane) * 16);
                uint4 v1 = *(const uint4*)(stA + ((mtl * 4 + 2 * kp + 1) * 32 + lane) * 16);
                a0[i][0]=v0.x; a0[i][1]=v0.y; a0[i][2]=v0.z; a0[i][3]=v0.w;
                a1[i][0]=v1.x; a1[i][1]=v1.y; a1[i][2]=v1.z; a1[i][3]=v1.w;
            }
#pragma unroll
            for (int j = 0; j < 4; j++) {
                int ntl = wn * 4 + j;
                uint4 b4 = *(const uint4*)(stB + ((ntl * 2 + kp) * 32 + lane) * 16);
#pragma unroll
                for (int i = 0; i < 4; i++) {
                    mma16(d[i][j], a0[i], b4.x, b4.y);
                    mma16(d[i][j], a1[i], b4.z, b4.w);
                }
            }
        }
    }

    // ---- epilogue: +bias, 0.5x for f-half ----
    const int g  = lane >> 2, tg = lane & 3;
    const int n0f = nt0 * 8;                   // multiple of 128
    const bool isF = (n0f >= HID);
    float*       outp  = isF ? g_f : g_z;
    const float* bp    = isF ? bfb : bz;
    const float  scale = isF ? 0.5f : 1.0f;
    const int colBase  = (n0f - (isF ? HID : 0)) + wn * 32;

#pragma unroll
    for (int j = 0; j < 4; j++) {
        const int col = colBase + j * 8 + 2 * tg;
        const float2 bbv = *(const float2*)(bp + col);
#pragma unroll
        for (int i = 0; i < 4; i++) {
            const size_t row = (size_t)blockIdx.y * BM + wm * 64 + i * 16 + g;
            float2 v0, v1;
            v0.x = scale * (d[i][j][0] + bbv.x);
            v0.y = scale * (d[i][j][1] + bbv.y);
            v1.x = scale * (d[i][j][2] + bbv.x);
            v1.y = scale * (d[i][j][3] + bbv.y);
            *(float2*)(outp + row * HID + col)       = v0;
            *(float2*)(outp + (row + 8) * HID + col) = v1;
        }
    }
}

// ============ scan: cp.async ring, 1 ch/thread, 128 thr/block ============
#define PF 32

__device__ __forceinline__ float tanh_fast(float v) {
    float r;
    asm("tanh.approx.f32 %0, %1;" : "=f"(r) : "f"(v));
    return r;
}

__global__ __launch_bounds__(128)
void scan_kernel(const float* __restrict__ state,
                 const float* __restrict__ wvz, const float* __restrict__ wvf,
                 float* __restrict__ out) {
    __shared__ float buf[PF][128][2];   // [stage][thread][0=z,1=f] = 32KB
    const int t = threadIdx.x;
    const int C = blockIdx.x * 128 + t;
    const int h0 = C & (HID - 1);

    float cell = state[C];
    const float wz  = wvz[h0];
    const float wfh = 0.5f * wvf[h0];

    const float* zsrc = g_z + C;
    const float* fsrc = g_f + C;

#pragma unroll 4
    for (int s = 0; s < PF; s++) {
        cp4((uint32_t)__cvta_generic_to_shared(&buf[s][t][0]), zsrc + (size_t)s * M_TOTAL);
        cp4((uint32_t)__cvta_generic_to_shared(&buf[s][t][1]), fsrc + (size_t)s * M_TOTAL);
        asm volatile("cp.async.commit_group;" ::: "memory");
    }

#pragma unroll 1
    for (int s = 0; s < SLEN; s++) {
        asm volatile("cp.async.wait_group %0;" :: "n"(PF - 1) : "memory");
        const int slot = s & (PF - 1);
        float zv = buf[slot][t][0];
        float fv = buf[slot][t][1];
        if (s + PF < SLEN) {
            cp4((uint32_t)__cvta_generic_to_shared(&buf[slot][t][0]),
                zsrc + (size_t)(s + PF) * M_TOTAL);
            cp4((uint32_t)__cvta_generic_to_shared(&buf[slot][t][1]),
                fsrc + (size_t)(s + PF) * M_TOTAL);
        }
        asm volatile("cp.async.commit_group;" ::: "memory");

        float zpart = tanh_fast(fmaf(wz,  cell, zv));
        float tt    = tanh_fast(fmaf(wfh, cell, fv));
        float fpart = fmaf(0.5f, tt, 0.5f);
        cell = fmaf(fpart, cell - zpart, zpart);
        out[(size_t)s * M_TOTAL + C] = cell;
    }
}

// ============ launch ============
extern "C" void kernel_launch(void* const* d_in, const int* in_sizes, int n_in,
                              void* d_out, int out_size) {
    const float* x      = (const float*)d_in[0];
    const float* state  = (const float*)d_in[1];
    const float* wm_z   = (const float*)d_in[2];
    const float* wm_f   = (const float*)d_in[3];
    const float* wv_z   = (const float*)d_in[4];
    const float* wv_f   = (const float*)d_in[5];
    const float* bias_z = (const float*)d_in[6];
    const float* bias_f = (const float*)d_in[7];
    float* out = (float*)d_out;

    uint4 *af, *bf;
    cudaGetSymbolAddress((void**)&af, g_ah);
    cudaGetSymbolAddress((void**)&bf, g_bh);

    cudaFuncSetAttribute(gemm_tc, cudaFuncAttributeMaxDynamicSharedMemorySize, SMEM_BYTES);

    prep_a<<<16384, 256>>>(x, af);
    prep_b<<<1024, 256>>>(wm_z, wm_f, bf);

    dim3 grid(NFUSED / BN, M_TOTAL / BM);   // (16, 256)
    gemm_tc<<<grid, 256, SMEM_BYTES>>>(af, bf, bias_z, bias_f);

    scan_kernel<<<256, 128>>>(state, wv_z, wv_f, out);
}